// round 14
// baseline (speedup 1.0000x reference)
#include <cuda_runtime.h>
#include <cuda_bf16.h>
#include <cstdint>

// ===========================================================================
// CrossModalAttention collapses analytically:
//   fa[b,s,:] constant over s => K_a, V_a constant over t
//   => softmax uniform => attn_out[b,s,:] == va[b,:]
//   => out = text @ Wt + bt + va[b]      (one real GEMM)
// GEMM on tensor cores via bf16x3 fp32 emulation (Ah*Bh + Ah*Bl + Al*Bh).
// Round 14: split_text ELIMINATED. The GEMM cp.asyncs raw fp32 text (same
// byte count as Ah+Al) and converts to bf16 hi/lo IN PLACE in smem once per
// chunk (read-all -> barrier -> write-all). Mainloop = round-4 best config
// (CTA 256x128, 512 thr, 64x32 warp tiles, KT=64, 2-stage). Prep is now just
// wsplit + va (~8us).
// ===========================================================================

#define BATCH 8
#define SEQ   2048
#define DM    768
#define DAUD  16
#define M_TOT (BATCH * SEQ)

__device__ float g_va[BATCH * DM];
__device__ __nv_bfloat16 g_Bh[DM * DM];     // Wt transposed: [N, K]
__device__ __nv_bfloat16 g_Bl[DM * DM];

// ------------------------------ helpers ------------------------------------
__device__ __forceinline__ uint32_t smem_u32(const void* p) {
    uint32_t r;
    asm("{ .reg .u64 t; cvta.to.shared.u64 t, %1; cvt.u32.u64 %0, t; }"
        : "=r"(r) : "l"(p));
    return r;
}

#define SWZ(o) ((o) ^ (((o) >> 3) & 0x70))

__device__ __forceinline__ void cpasync16(uint32_t dst, const void* src) {
    asm volatile("cp.async.cg.shared.global [%0], [%1], 16;"
                 :: "r"(dst), "l"(src));
}

__device__ __forceinline__ void ldsm4(uint32_t* r, uint32_t addr) {
    asm volatile("ldmatrix.sync.aligned.m8n8.x4.shared.b16 {%0,%1,%2,%3}, [%4];"
                 : "=r"(r[0]), "=r"(r[1]), "=r"(r[2]), "=r"(r[3])
                 : "r"(addr));
}

__device__ __forceinline__ void mma16816(float* d,
                                         const uint32_t* a,
                                         uint32_t b0, uint32_t b1) {
    asm volatile(
        "mma.sync.aligned.m16n8k16.row.col.f32.bf16.bf16.f32 "
        "{%0,%1,%2,%3}, {%4,%5,%6,%7}, {%8,%9}, {%0,%1,%2,%3};"
        : "+f"(d[0]), "+f"(d[1]), "+f"(d[2]), "+f"(d[3])
        : "r"(a[0]), "r"(a[1]), "r"(a[2]), "r"(a[3]), "r"(b0), "r"(b1));
}

__device__ __forceinline__ void lds128(float4& v, uint32_t addr) {
    asm volatile("ld.shared.v4.f32 {%0,%1,%2,%3}, [%4];"
                 : "=f"(v.x), "=f"(v.y), "=f"(v.z), "=f"(v.w) : "r"(addr));
}

__device__ __forceinline__ void sts64(uint32_t addr, uint32_t a, uint32_t b) {
    asm volatile("st.shared.v2.b32 [%0], {%1,%2};"
                 :: "r"(addr), "r"(a), "r"(b) : "memory");
}

__device__ __forceinline__ uint32_t cvt_bf16x2(float hi, float lo) {
    uint32_t r;  // packs lo into bits[0:16), hi into [16:32)
    asm("cvt.rn.bf16x2.f32 %0, %1, %2;" : "=r"(r) : "f"(hi), "f"(lo));
    return r;
}

// ---------------------------------------------------------------------------
// Prep B: transpose + split Wt[K,N] -> g_Bh/g_Bl [N,K]
// ---------------------------------------------------------------------------
__global__ void wsplit_kernel(const float* __restrict__ W) {
    __shared__ float tile[32][33];
    int n0 = blockIdx.x * 32, k0 = blockIdx.y * 32;
    int tx = threadIdx.x, ty = threadIdx.y;
    for (int r = ty; r < 32; r += 8)
        tile[r][tx] = W[(size_t)(k0 + r) * DM + n0 + tx];
    __syncthreads();
    for (int r = ty; r < 32; r += 8) {
        float v = tile[tx][r];                 // = W[k0+tx][n0+r]
        __nv_bfloat16 h = __float2bfloat16(v);
        __nv_bfloat16 l = __float2bfloat16(v - __bfloat162float(h));
        g_Bh[(size_t)(n0 + r) * DM + k0 + tx] = h;
        g_Bl[(size_t)(n0 + r) * DM + k0 + tx] = l;
    }
}

// ---------------------------------------------------------------------------
// Prep C: va[b,:] = (acoustic[b,:] @ Wa + ba) @ Wv + bv
// ---------------------------------------------------------------------------
__global__ void va_kernel(const float* __restrict__ ac,
                          const float* __restrict__ Wa,
                          const float* __restrict__ ba,
                          const float* __restrict__ Wv,
                          const float* __restrict__ bv) {
    __shared__ float fa[DM];
    __shared__ float acs[DAUD];
    const int b = blockIdx.x;
    const int t = threadIdx.x;
    if (t < DAUD) acs[t] = ac[b * DAUD + t];
    __syncthreads();
    float v = ba[t];
#pragma unroll
    for (int k = 0; k < DAUD; k++) v += acs[k] * Wa[k * DM + t];
    fa[t] = v;
    __syncthreads();
    float o = bv[t];
    for (int e = 0; e < DM; e++) o += fa[e] * Wv[e * DM + t];
    g_va[b * DM + t] = o;
}

// ---------------------------------------------------------------------------
// GEMM: CTA tile 256x128, 512 threads (16 warps, 4x4), warp tile 64x32.
// KT=64 chunks, 2-stage cp.async ring.
// Stage layout (96 KB): [0:64K) A fp32 (converted in place to Ah[0:32K) +
// Al[32K:64K)), [64K:80K) Bh, [80K:96K) Bl.
// ---------------------------------------------------------------------------
#define BM      256
#define BN      128
#define KT      64
#define KSTEPS  4
#define NCHUNK  (DM / KT)                 // 12
#define A_BYTES (BM * KT * 4)             // 64 KB fp32 (== Ah+Al bf16)
#define AH_OFF  0
#define AL_OFF  (BM * KT * 2)             // 32 KB
#define TILE_B  (BN * 128)                // 16 KB
#define BH_OFF  A_BYTES
#define BL_OFF  (A_BYTES + TILE_B)
#define STAGEB  (A_BYTES + 2 * TILE_B)    // 96 KB
#define SMEM_DYN (2 * STAGEB + 1024)

__device__ __forceinline__ void load_chunk(uint32_t stg,
                                           const float* __restrict__ gA,
                                           const __nv_bfloat16* __restrict__ gBh,
                                           const __nv_bfloat16* __restrict__ gBl,
                                           int k0, int tid) {
    // A fp32: 4096 units of 16B, linear layout (256B per row of 64 fp32)
#pragma unroll
    for (int j = 0; j < 8; j++) {
        const int u = tid + j * 512;              // 0..4095
        const int row = u >> 4, c16 = u & 15;
        cpasync16(stg + row * 256 + c16 * 16,
                  gA + (size_t)row * DM + k0 + c16 * 4);
    }
    // B hi/lo: 1024 units each, SW128-swizzled 128B rows
    const __nv_bfloat16* gb[2] = {gBh, gBl};
#pragma unroll
    for (int t = 0; t < 2; t++) {
        const uint32_t tb = stg + BH_OFF + t * TILE_B;
#pragma unroll
        for (int j = 0; j < 2; j++) {
            const int q = tid + j * 512;          // 0..1023
            const int row = q >> 3, cc = q & 7;
            cpasync16(tb + SWZ(row * 128 + cc * 16),
                      gb[t] + (size_t)row * DM + k0 + cc * 8);
        }
    }
    asm volatile("cp.async.commit_group;");
}

__global__ __launch_bounds__(512, 1)
void gemm_kernel(const float* __restrict__ text,
                 const float* __restrict__ bias, float* __restrict__ out) {
    extern __shared__ char dynsmem[];
    uint32_t base = smem_u32(dynsmem);
    base = (base + 1023u) & ~1023u;

    const int tid = threadIdx.x;
    const int wid = tid >> 5, lane = tid & 31;
    const int wm = wid >> 2, wn = wid & 3;   // 4x4 warp grid
    const int bn = blockIdx.x, bm = blockIdx.y;

    const float* gA = text + (size_t)bm * BM * DM;
    const __nv_bfloat16* gBh = g_Bh + (size_t)bn * BN * DM;
    const __nv_bfloat16* gBl = g_Bl + (size_t)bn * BN * DM;

    float acc[4][4][4] = {};

    load_chunk(base + 0 * STAGEB, gA, gBh, gBl, 0 * KT, tid);
    load_chunk(base + 1 * STAGEB, gA, gBh, gBl, 1 * KT, tid);

    for (int c = 0; c < NCHUNK; ++c) {
        asm volatile("cp.async.wait_group 1;");
        __syncthreads();

        const uint32_t stg = base + (c & 1) * STAGEB;

        // ---- in-place fp32 -> bf16 hi/lo conversion of the A chunk ----
        // Read all 32 fp32 into registers first (writes overwrite the
        // fp32 region), then barrier, then write hi/lo.
        float4 t[8];
#pragma unroll
        for (int j = 0; j < 8; j++) {
            const int u = tid + j * 512;
            lds128(t[j], stg + (u >> 4) * 256 + (u & 15) * 16);
        }
        __syncthreads();
#pragma unroll
        for (int j = 0; j < 8; j++) {
            const int u = tid + j * 512;
            const uint32_t o = SWZ((u >> 4) * 128 + (u & 15) * 8);
            const uint32_t h01 = cvt_bf16x2(t[j].y, t[j].x);
            const uint32_t h23 = cvt_bf16x2(t[j].w, t[j].z);
            const float l0 = t[j].x - __uint_as_float(h01 << 16);
            const float l1 = t[j].y - __uint_as_float(h01 & 0xFFFF0000u);
            const float l2 = t[j].z - __uint_as_float(h23 << 16);
            const float l3 = t[j].w - __uint_as_float(h23 & 0xFFFF0000u);
            sts64(stg + AH_OFF + o, h01, h23);
            sts64(stg + AL_OFF + o, cvt_bf16x2(l1, l0), cvt_bf16x2(l3, l2));
        }
        __syncthreads();

        // ---- round-4 mainloop on converted Ah/Al + loaded Bh/Bl ----
        const uint32_t Ah = stg + AH_OFF, Al = stg + AL_OFF;
        const uint32_t Bh = stg + BH_OFF, Bl = stg + BL_OFF;

#pragma unroll
        for (int ks = 0; ks < KSTEPS; ks++) {
            uint32_t ah[4][4], al[4][4];
            const int akb = ks * 32 + (lane >> 4) * 16;
#pragma unroll
            for (int mt = 0; mt < 4; mt++) {
                const int row = wm * 64 + mt * 16 + (lane & 15);
                const uint32_t off = SWZ(row * 128 + akb);
                ldsm4(ah[mt], Ah + off);
                ldsm4(al[mt], Al + off);
            }
            const int brow_base = wn * 32 + (lane & 7) + ((lane >> 4) << 3);
            const int bkb = ks * 32 + ((lane >> 3) & 1) * 16;
#pragma unroll
            for (int p = 0; p < 2; p++) {
                uint32_t bh[4], bl[4];
                const uint32_t off = SWZ((brow_base + p * 16) * 128 + bkb);
                ldsm4(bh, Bh + off);
                ldsm4(bl, Bl + off);
#pragma unroll
                for (int mt = 0; mt < 4; mt++) {
                    float* d0 = acc[mt][2 * p];
                    float* d1 = acc[mt][2 * p + 1];
                    mma16816(d0, ah[mt], bh[0], bh[1]);
                    mma16816(d1, ah[mt], bh[2], bh[3]);
                    mma16816(d0, ah[mt], bl[0], bl[1]);
                    mma16816(d1, ah[mt], bl[2], bl[3]);
                    mma16816(d0, al[mt], bh[0], bh[1]);
                    mma16816(d1, al[mt], bh[2], bh[3]);
                }
            }
        }
        __syncthreads();
        if (c + 2 < NCHUNK)
            load_chunk(stg, gA, gBh, gBl, (c + 2) * KT, tid);
        else
            asm volatile("cp.async.commit_group;");   // keep group count in step
    }

    // Epilogue: out = acc + bias + va[b].  BM=256 -> bidx = bm >> 3.
    const int bidx = bm >> 3;
#pragma unroll
    for (int mt = 0; mt < 4; mt++) {
        const int r0 = bm * BM + wm * 64 + mt * 16 + (lane >> 2);
#pragma unroll
        for (int nt = 0; nt < 4; nt++) {
            const int col = bn * BN + wn * 32 + nt * 8 + (lane & 3) * 2;
            const float bv0 = bias[col]     + g_va[bidx * DM + col];
            const float bv1 = bias[col + 1] + g_va[bidx * DM + col + 1];
            float2 v0, v1;
            v0.x = acc[mt][nt][0] + bv0;  v0.y = acc[mt][nt][1] + bv1;
            v1.x = acc[mt][nt][2] + bv0;  v1.y = acc[mt][nt][3] + bv1;
            *(float2*)(out + (size_t)r0 * DM + col)       = v0;
            *(float2*)(out + (size_t)(r0 + 8) * DM + col) = v1;
        }
    }
}

// ---------------------------------------------------------------------------
// Launch. Input order: text, acoustic, Wt, bt, Wa, ba, Wq,bq, Wk,bk, Wv,bv
// ---------------------------------------------------------------------------
extern "C" void kernel_launch(void* const* d_in, const int* in_sizes, int n_in,
                              void* d_out, int out_size) {
    const float* text = (const float*)d_in[0];
    const float* ac   = (const float*)d_in[1];
    const float* Wt   = (const float*)d_in[2];
    const float* bt   = (const float*)d_in[3];
    const float* Wa   = (const float*)d_in[4];
    const float* ba   = (const float*)d_in[5];
    const float* Wv   = (const float*)d_in[10];
    const float* bv   = (const float*)d_in[11];
    float* out = (float*)d_out;

    cudaFuncSetAttribute(gemm_kernel,
                         cudaFuncAttributeMaxDynamicSharedMemorySize, SMEM_DYN);

    wsplit_kernel<<<dim3(DM / 32, DM / 32), dim3(32, 8)>>>(Wt);
    va_kernel<<<BATCH, DM>>>(ac, Wa, ba, Wv, bv);

    gemm_kernel<<<dim3(DM / BN, M_TOT / BM), 512, SMEM_DYN>>>(text, bt, out);
}

// round 15
// speedup vs baseline: 1.3868x; 1.3868x over previous
#include <cuda_runtime.h>
#include <cuda_fp16.h>
#include <cstdint>

// ===========================================================================
// CrossModalAttention collapses analytically:
//   fa[b,s,:] constant over s => K_a, V_a constant over t
//   => softmax uniform => attn_out[b,s,:] == va[b,:]
//   => out = text @ Wt + bt + va[b]      (one real GEMM)
// Round 15: asymmetric fp16 2-product emulation. B (weights) split into
// fp16 hi/lo in prep (fully represented, ~2^-22); A (text) as single fp16
// (err 2^-11 ~ 3-6e-4 << 1e-3 tolerance).  D = Ah*Bh + Ah*Bl: 2 MMA
// products instead of bf16x3's 3, and one A fragment per k-step instead of
// two (LDSM 12 -> 8 per k-step). Mainloop skeleton = round-4 best config
// (CTA 256x128, 512 thr, 4x4 warps, 64x32 warp tile, KT=64, 2-stage).
// ===========================================================================

#define BATCH 8
#define SEQ   2048
#define DM    768
#define DAUD  16
#define M_TOT (BATCH * SEQ)

__device__ float g_va[BATCH * DM];
__device__ __half g_A [M_TOT * DM];        // text as fp16
__device__ __half g_Bh[DM * DM];           // Wt transposed [N,K], fp16 hi
__device__ __half g_Bl[DM * DM];           // fp16 lo

// ------------------------------ helpers ------------------------------------
__device__ __forceinline__ uint32_t smem_u32(const void* p) {
    uint32_t r;
    asm("{ .reg .u64 t; cvta.to.shared.u64 t, %1; cvt.u32.u64 %0, t; }"
        : "=r"(r) : "l"(p));
    return r;
}

#define SWZ(o) ((o) ^ (((o) >> 3) & 0x70))

__device__ __forceinline__ void cpasync16(uint32_t dst, const void* src) {
    asm volatile("cp.async.cg.shared.global [%0], [%1], 16;"
                 :: "r"(dst), "l"(src));
}

__device__ __forceinline__ void ldsm4(uint32_t* r, uint32_t addr) {
    asm volatile("ldmatrix.sync.aligned.m8n8.x4.shared.b16 {%0,%1,%2,%3}, [%4];"
                 : "=r"(r[0]), "=r"(r[1]), "=r"(r[2]), "=r"(r[3])
                 : "r"(addr));
}

__device__ __forceinline__ void mma16816(float* d,
                                         const uint32_t* a,
                                         uint32_t b0, uint32_t b1) {
    asm volatile(
        "mma.sync.aligned.m16n8k16.row.col.f32.f16.f16.f32 "
        "{%0,%1,%2,%3}, {%4,%5,%6,%7}, {%8,%9}, {%0,%1,%2,%3};"
        : "+f"(d[0]), "+f"(d[1]), "+f"(d[2]), "+f"(d[3])
        : "r"(a[0]), "r"(a[1]), "r"(a[2]), "r"(a[3]), "r"(b0), "r"(b1));
}

__device__ __forceinline__ void stg_cs_v2(float* p, float x, float y) {
    asm volatile("st.global.cs.v2.f32 [%0], {%1, %2};"
                 :: "l"(p), "f"(x), "f"(y) : "memory");
}

// ---------------------------------------------------------------------------
// Prep A: fp32 text -> fp16, 8 elems/thread, one 16B store.
// ---------------------------------------------------------------------------
__global__ void split_text_kernel(const float* __restrict__ x) {
    size_t i = ((size_t)blockIdx.x * blockDim.x + threadIdx.x) * 8;
    float4 v0 = *(const float4*)(x + i);
    float4 v1 = *(const float4*)(x + i + 4);
    __half2 h[4];
    h[0] = __float22half2_rn(make_float2(v0.x, v0.y));
    h[1] = __float22half2_rn(make_float2(v0.z, v0.w));
    h[2] = __float22half2_rn(make_float2(v1.x, v1.y));
    h[3] = __float22half2_rn(make_float2(v1.z, v1.w));
    *(uint4*)(g_A + i) = *(const uint4*)h;
}

// ---------------------------------------------------------------------------
// Prep B: transpose + fp16 hi/lo split Wt[K,N] -> g_Bh/g_Bl [N,K]
// ---------------------------------------------------------------------------
__global__ void wsplit_kernel(const float* __restrict__ W) {
    __shared__ float tile[32][33];
    int n0 = blockIdx.x * 32, k0 = blockIdx.y * 32;
    int tx = threadIdx.x, ty = threadIdx.y;
    for (int r = ty; r < 32; r += 8)
        tile[r][tx] = W[(size_t)(k0 + r) * DM + n0 + tx];
    __syncthreads();
    for (int r = ty; r < 32; r += 8) {
        float v = tile[tx][r];                 // = W[k0+tx][n0+r]
        __half h = __float2half_rn(v);
        __half l = __float2half_rn(v - __half2float(h));
        g_Bh[(size_t)(n0 + r) * DM + k0 + tx] = h;
        g_Bl[(size_t)(n0 + r) * DM + k0 + tx] = l;
    }
}

// ---------------------------------------------------------------------------
// Prep C: va[b,:] = (acoustic[b,:] @ Wa + ba) @ Wv + bv
// ---------------------------------------------------------------------------
__global__ void va_kernel(const float* __restrict__ ac,
                          const float* __restrict__ Wa,
                          const float* __restrict__ ba,
                          const float* __restrict__ Wv,
                          const float* __restrict__ bv) {
    __shared__ float fa[DM];
    __shared__ float acs[DAUD];
    const int b = blockIdx.x;
    const int t = threadIdx.x;
    if (t < DAUD) acs[t] = ac[b * DAUD + t];
    __syncthreads();
    float v = ba[t];
#pragma unroll
    for (int k = 0; k < DAUD; k++) v += acs[k] * Wa[k * DM + t];
    fa[t] = v;
    __syncthreads();
    float o = bv[t];
    for (int e = 0; e < DM; e++) o += fa[e] * Wv[e * DM + t];
    g_va[b * DM + t] = o;
}

// ---------------------------------------------------------------------------
// GEMM: CTA tile 256x128, 512 threads (16 warps, 4x4), warp tile 64x32.
// KT=64 chunks, 2-stage cp.async ring, SW128 smem.
// Stage (64 KB): A fp16 [256x64] 32 KB, Bh 16 KB, Bl 16 KB.
// ---------------------------------------------------------------------------
#define BM      256
#define BN      128
#define KT      64
#define KSTEPS  4
#define NCHUNK  (DM / KT)                 // 12
#define TILE_A  (BM * 128)                // 32 KB (256 rows x 128B)
#define TILE_B  (BN * 128)                // 16 KB
#define STAGEB  (TILE_A + 2 * TILE_B)     // 64 KB
#define SMEM_DYN (2 * STAGEB + 1024)

__device__ __forceinline__ void load_chunk(uint32_t stg,
                                           const __half* __restrict__ gA,
                                           const __half* __restrict__ gBh,
                                           const __half* __restrict__ gBl,
                                           int k0, int tid) {
    // A: 2048 x 16B lines (32 KB)
#pragma unroll
    for (int j = 0; j < 4; j++) {
        const int q = tid + j * 512;              // 0..2047
        const int row = q >> 3, cc = q & 7;
        cpasync16(stg + SWZ(row * 128 + cc * 16),
                  gA + (size_t)row * DM + k0 + cc * 8);
    }
    // B hi/lo: 1024 lines each
    const __half* gb[2] = {gBh, gBl};
#pragma unroll
    for (int t = 0; t < 2; t++) {
        const uint32_t tb = stg + TILE_A + t * TILE_B;
#pragma unroll
        for (int j = 0; j < 2; j++) {
            const int q = tid + j * 512;          // 0..1023
            const int row = q >> 3, cc = q & 7;
            cpasync16(tb + SWZ(row * 128 + cc * 16),
                      gb[t] + (size_t)row * DM + k0 + cc * 8);
        }
    }
    asm volatile("cp.async.commit_group;");
}

__global__ __launch_bounds__(512, 1)
void gemm_kernel(const float* __restrict__ bias, float* __restrict__ out) {
    extern __shared__ char dynsmem[];
    uint32_t base = smem_u32(dynsmem);
    base = (base + 1023u) & ~1023u;

    const int tid = threadIdx.x;
    const int wid = tid >> 5, lane = tid & 31;
    const int wm = wid >> 2, wn = wid & 3;   // 4x4 warp grid
    const int bn = blockIdx.x, bm = blockIdx.y;

    const __half* gA  = g_A  + (size_t)bm * BM * DM;
    const __half* gBh = g_Bh + (size_t)bn * BN * DM;
    const __half* gBl = g_Bl + (size_t)bn * BN * DM;

    float acc[4][4][4] = {};

    load_chunk(base + 0 * STAGEB, gA, gBh, gBl, 0 * KT, tid);
    load_chunk(base + 1 * STAGEB, gA, gBh, gBl, 1 * KT, tid);

    // Prefetch epilogue addends while the pipeline fills.
    const int bidx = bm >> 3;                // (bm*256)/2048
    float addv[4][2];
#pragma unroll
    for (int nt = 0; nt < 4; nt++) {
        const int col = bn * BN + wn * 32 + nt * 8 + (lane & 3) * 2;
        addv[nt][0] = bias[col]     + g_va[bidx * DM + col];
        addv[nt][1] = bias[col + 1] + g_va[bidx * DM + col + 1];
    }

    for (int c = 0; c < NCHUNK; ++c) {
        asm volatile("cp.async.wait_group 1;");
        __syncthreads();

        const uint32_t stg = base + (c & 1) * STAGEB;
        const uint32_t Ah = stg;
        const uint32_t Bh = stg + TILE_A, Bl = Bh + TILE_B;

#pragma unroll
        for (int ks = 0; ks < KSTEPS; ks++) {
            uint32_t ah[4][4];
            const int akb = ks * 32 + (lane >> 4) * 16;
#pragma unroll
            for (int mt = 0; mt < 4; mt++) {
                const int row = wm * 64 + mt * 16 + (lane & 15);
                ldsm4(ah[mt], Ah + SWZ(row * 128 + akb));
            }
            const int brow_base = wn * 32 + (lane & 7) + ((lane >> 4) << 3);
            const int bkb = ks * 32 + ((lane >> 3) & 1) * 16;
#pragma unroll
            for (int p = 0; p < 2; p++) {
                uint32_t bh[4], bl[4];
                const uint32_t off = SWZ((brow_base + p * 16) * 128 + bkb);
                ldsm4(bh, Bh + off);
                ldsm4(bl, Bl + off);
#pragma unroll
                for (int mt = 0; mt < 4; mt++) {
                    float* d0 = acc[mt][2 * p];
                    float* d1 = acc[mt][2 * p + 1];
                    mma16816(d0, ah[mt], bh[0], bh[1]);
                    mma16816(d1, ah[mt], bh[2], bh[3]);
                    mma16816(d0, ah[mt], bl[0], bl[1]);
                    mma16816(d1, ah[mt], bl[2], bl[3]);
                }
            }
        }
        __syncthreads();
        if (c + 2 < NCHUNK)
            load_chunk(stg, gA, gBh, gBl, (c + 2) * KT, tid);
        else
            asm volatile("cp.async.commit_group;");   // keep group count in step
    }

    // Epilogue: out = acc + (bias + va), streaming stores.
#pragma unroll
    for (int mt = 0; mt < 4; mt++) {
        const int r0 = bm * BM + wm * 64 + mt * 16 + (lane >> 2);
#pragma unroll
        for (int nt = 0; nt < 4; nt++) {
            const int col = bn * BN + wn * 32 + nt * 8 + (lane & 3) * 2;
            stg_cs_v2(out + (size_t)r0 * DM + col,
                      acc[mt][nt][0] + addv[nt][0],
                      acc[mt][nt][1] + addv[nt][1]);
            stg_cs_v2(out + (size_t)(r0 + 8) * DM + col,
                      acc[mt][nt][2] + addv[nt][0],
                      acc[mt][nt][3] + addv[nt][1]);
        }
    }
}

// ---------------------------------------------------------------------------
// Launch. Input order: text, acoustic, Wt, bt, Wa, ba, Wq,bq, Wk,bk, Wv,bv
// ---------------------------------------------------------------------------
extern "C" void kernel_launch(void* const* d_in, const int* in_sizes, int n_in,
                              void* d_out, int out_size) {
    const float* text = (const float*)d_in[0];
    const float* ac   = (const float*)d_in[1];
    const float* Wt   = (const float*)d_in[2];
    const float* bt   = (const float*)d_in[3];
    const float* Wa   = (const float*)d_in[4];
    const float* ba   = (const float*)d_in[5];
    const float* Wv   = (const float*)d_in[10];
    const float* bv   = (const float*)d_in[11];
    float* out = (float*)d_out;

    cudaFuncSetAttribute(gemm_kernel,
                         cudaFuncAttributeMaxDynamicSharedMemorySize, SMEM_DYN);

    split_text_kernel<<<(M_TOT * DM) / 8 / 256, 256>>>(text);
    wsplit_kernel<<<dim3(DM / 32, DM / 32), dim3(32, 8)>>>(Wt);
    va_kernel<<<BATCH, DM>>>(ac, Wa, ba, Wv, bv);

    gemm_kernel<<<dim3(DM / BN, M_TOT / BM), 512, SMEM_DYN>>>(bt, out);
}

// round 16
// speedup vs baseline: 1.9321x; 1.3932x over previous
#include <cuda_runtime.h>
#include <cuda_fp16.h>
#include <cstdint>

// ===========================================================================
// CrossModalAttention collapses analytically:
//   fa[b,s,:] constant over s => K_a, V_a constant over t
//   => softmax uniform => attn_out[b,s,:] == va[b,:]
//   => out = text @ Wt + bt + va[b]      (one real GEMM)
// Round 16: pure fp16 single-product GEMM. A and B both fp16 (independent
// rounding errors ~1.8e-4 each, RSS ~2.5e-4 << 1e-3 tolerance). Halves MMA
// count and B traffic vs round 15's 2-product. Mainloop skeleton unchanged
// (CTA 256x128, 512 thr, 4x4 warps, 64x32 warp tile, KT=64, 2-stage).
// ===========================================================================

#define BATCH 8
#define SEQ   2048
#define DM    768
#define DAUD  16
#define M_TOT (BATCH * SEQ)

__device__ float g_va[BATCH * DM];
__device__ __half g_A[M_TOT * DM];         // text as fp16
__device__ __half g_B[DM * DM];            // Wt transposed [N,K], fp16

// ------------------------------ helpers ------------------------------------
__device__ __forceinline__ uint32_t smem_u32(const void* p) {
    uint32_t r;
    asm("{ .reg .u64 t; cvta.to.shared.u64 t, %1; cvt.u32.u64 %0, t; }"
        : "=r"(r) : "l"(p));
    return r;
}

#define SWZ(o) ((o) ^ (((o) >> 3) & 0x70))

__device__ __forceinline__ void cpasync16(uint32_t dst, const void* src) {
    asm volatile("cp.async.cg.shared.global [%0], [%1], 16;"
                 :: "r"(dst), "l"(src));
}

__device__ __forceinline__ void ldsm4(uint32_t* r, uint32_t addr) {
    asm volatile("ldmatrix.sync.aligned.m8n8.x4.shared.b16 {%0,%1,%2,%3}, [%4];"
                 : "=r"(r[0]), "=r"(r[1]), "=r"(r[2]), "=r"(r[3])
                 : "r"(addr));
}

__device__ __forceinline__ void mma16816(float* d,
                                         const uint32_t* a,
                                         uint32_t b0, uint32_t b1) {
    asm volatile(
        "mma.sync.aligned.m16n8k16.row.col.f32.f16.f16.f32 "
        "{%0,%1,%2,%3}, {%4,%5,%6,%7}, {%8,%9}, {%0,%1,%2,%3};"
        : "+f"(d[0]), "+f"(d[1]), "+f"(d[2]), "+f"(d[3])
        : "r"(a[0]), "r"(a[1]), "r"(a[2]), "r"(a[3]), "r"(b0), "r"(b1));
}

__device__ __forceinline__ void stg_cs_v2(float* p, float x, float y) {
    asm volatile("st.global.cs.v2.f32 [%0], {%1, %2};"
                 :: "l"(p), "f"(x), "f"(y) : "memory");
}

// ---------------------------------------------------------------------------
// Prep A: fp32 text -> fp16, 8 elems/thread, one 16B store.
// ---------------------------------------------------------------------------
__global__ void split_text_kernel(const float* __restrict__ x) {
    size_t i = ((size_t)blockIdx.x * blockDim.x + threadIdx.x) * 8;
    float4 v0 = *(const float4*)(x + i);
    float4 v1 = *(const float4*)(x + i + 4);
    __half2 h[4];
    h[0] = __float22half2_rn(make_float2(v0.x, v0.y));
    h[1] = __float22half2_rn(make_float2(v0.z, v0.w));
    h[2] = __float22half2_rn(make_float2(v1.x, v1.y));
    h[3] = __float22half2_rn(make_float2(v1.z, v1.w));
    *(uint4*)(g_A + i) = *(const uint4*)h;
}

// ---------------------------------------------------------------------------
// Prep B: transpose + fp16 convert Wt[K,N] -> g_B [N,K]
// ---------------------------------------------------------------------------
__global__ void wsplit_kernel(const float* __restrict__ W) {
    __shared__ float tile[32][33];
    int n0 = blockIdx.x * 32, k0 = blockIdx.y * 32;
    int tx = threadIdx.x, ty = threadIdx.y;
    for (int r = ty; r < 32; r += 8)
        tile[r][tx] = W[(size_t)(k0 + r) * DM + n0 + tx];
    __syncthreads();
    for (int r = ty; r < 32; r += 8)
        g_B[(size_t)(n0 + r) * DM + k0 + tx] = __float2half_rn(tile[tx][r]);
}

// ---------------------------------------------------------------------------
// Prep C: va[b,:] = (acoustic[b,:] @ Wa + ba) @ Wv + bv
// ---------------------------------------------------------------------------
__global__ void va_kernel(const float* __restrict__ ac,
                          const float* __restrict__ Wa,
                          const float* __restrict__ ba,
                          const float* __restrict__ Wv,
                          const float* __restrict__ bv) {
    __shared__ float fa[DM];
    __shared__ float acs[DAUD];
    const int b = blockIdx.x;
    const int t = threadIdx.x;
    if (t < DAUD) acs[t] = ac[b * DAUD + t];
    __syncthreads();
    float v = ba[t];
#pragma unroll
    for (int k = 0; k < DAUD; k++) v += acs[k] * Wa[k * DM + t];
    fa[t] = v;
    __syncthreads();
    float o = bv[t];
    for (int e = 0; e < DM; e++) o += fa[e] * Wv[e * DM + t];
    g_va[b * DM + t] = o;
}

// ---------------------------------------------------------------------------
// GEMM: CTA tile 256x128, 512 threads (16 warps, 4x4), warp tile 64x32.
// KT=64 chunks, 2-stage cp.async ring, SW128 smem.
// Stage (48 KB): A fp16 [256x64] 32 KB, B fp16 [128x64] 16 KB.
// ---------------------------------------------------------------------------
#define BM      256
#define BN      128
#define KT      64
#define KSTEPS  4
#define NCHUNK  (DM / KT)                 // 12
#define TILE_A  (BM * 128)                // 32 KB (256 rows x 128B)
#define TILE_B  (BN * 128)                // 16 KB
#define STAGEB  (TILE_A + TILE_B)         // 48 KB
#define SMEM_DYN (2 * STAGEB + 1024)

__device__ __forceinline__ void load_chunk(uint32_t stg,
                                           const __half* __restrict__ gA,
                                           const __half* __restrict__ gB,
                                           int k0, int tid) {
    // A: 2048 x 16B lines (32 KB)
#pragma unroll
    for (int j = 0; j < 4; j++) {
        const int q = tid + j * 512;              // 0..2047
        const int row = q >> 3, cc = q & 7;
        cpasync16(stg + SWZ(row * 128 + cc * 16),
                  gA + (size_t)row * DM + k0 + cc * 8);
    }
    // B: 1024 lines
#pragma unroll
    for (int j = 0; j < 2; j++) {
        const int q = tid + j * 512;              // 0..1023
        const int row = q >> 3, cc = q & 7;
        cpasync16(stg + TILE_A + SWZ(row * 128 + cc * 16),
                  gB + (size_t)row * DM + k0 + cc * 8);
    }
    asm volatile("cp.async.commit_group;");
}

__global__ __launch_bounds__(512, 1)
void gemm_kernel(const float* __restrict__ bias, float* __restrict__ out) {
    extern __shared__ char dynsmem[];
    uint32_t base = smem_u32(dynsmem);
    base = (base + 1023u) & ~1023u;

    const int tid = threadIdx.x;
    const int wid = tid >> 5, lane = tid & 31;
    const int wm = wid >> 2, wn = wid & 3;   // 4x4 warp grid
    const int bn = blockIdx.x, bm = blockIdx.y;

    const __half* gA = g_A + (size_t)bm * BM * DM;
    const __half* gB = g_B + (size_t)bn * BN * DM;

    float acc[4][4][4] = {};

    load_chunk(base + 0 * STAGEB, gA, gB, 0 * KT, tid);
    load_chunk(base + 1 * STAGEB, gA, gB, 1 * KT, tid);

    // Prefetch epilogue addends while the pipeline fills.
    const int bidx = bm >> 3;                // (bm*256)/2048
    float addv[4][2];
#pragma unroll
    for (int nt = 0; nt < 4; nt++) {
        const int col = bn * BN + wn * 32 + nt * 8 + (lane & 3) * 2;
        addv[nt][0] = bias[col]     + g_va[bidx * DM + col];
        addv[nt][1] = bias[col + 1] + g_va[bidx * DM + col + 1];
    }

    for (int c = 0; c < NCHUNK; ++c) {
        asm volatile("cp.async.wait_group 1;");
        __syncthreads();

        const uint32_t stg = base + (c & 1) * STAGEB;
        const uint32_t As = stg;
        const uint32_t Bs = stg + TILE_A;

#pragma unroll
        for (int ks = 0; ks < KSTEPS; ks++) {
            uint32_t ah[4][4];
            const int akb = ks * 32 + (lane >> 4) * 16;
#pragma unroll
            for (int mt = 0; mt < 4; mt++) {
                const int row = wm * 64 + mt * 16 + (lane & 15);
                ldsm4(ah[mt], As + SWZ(row * 128 + akb));
            }
            const int brow_base = wn * 32 + (lane & 7) + ((lane >> 4) << 3);
            const int bkb = ks * 32 + ((lane >> 3) & 1) * 16;
#pragma unroll
            for (int p = 0; p < 2; p++) {
                uint32_t bh[4];
                ldsm4(bh, Bs + SWZ((brow_base + p * 16) * 128 + bkb));
#pragma unroll
                for (int mt = 0; mt < 4; mt++) {
                    mma16816(acc[mt][2 * p],     ah[mt], bh[0], bh[1]);
                    mma16816(acc[mt][2 * p + 1], ah[mt], bh[2], bh[3]);
                }
            }
        }
        __syncthreads();
        if (c + 2 < NCHUNK)
            load_chunk(stg, gA, gB, (c + 2) * KT, tid);
        else
            asm volatile("cp.async.commit_group;");   // keep group count in step
    }

    // Epilogue: out = acc + (bias + va), streaming stores.
#pragma unroll
    for (int mt = 0; mt < 4; mt++) {
        const int r0 = bm * BM + wm * 64 + mt * 16 + (lane >> 2);
#pragma unroll
        for (int nt = 0; nt < 4; nt++) {
            const int col = bn * BN + wn * 32 + nt * 8 + (lane & 3) * 2;
            stg_cs_v2(out + (size_t)r0 * DM + col,
                      acc[mt][nt][0] + addv[nt][0],
                      acc[mt][nt][1] + addv[nt][1]);
            stg_cs_v2(out + (size_t)(r0 + 8) * DM + col,
                      acc[mt][nt][2] + addv[nt][0],
                      acc[mt][nt][3] + addv[nt][1]);
        }
    }
}

// ---------------------------------------------------------------------------
// Launch. Input order: text, acoustic, Wt, bt, Wa, ba, Wq,bq, Wk,bk, Wv,bv
// ---------------------------------------------------------------------------
extern "C" void kernel_launch(void* const* d_in, const int* in_sizes, int n_in,
                              void* d_out, int out_size) {
    const float* text = (const float*)d_in[0];
    const float* ac   = (const float*)d_in[1];
    const float* Wt   = (const float*)d_in[2];
    const float* bt   = (const float*)d_in[3];
    const float* Wa   = (const float*)d_in[4];
    const float* ba   = (const float*)d_in[5];
    const float* Wv   = (const float*)d_in[10];
    const float* bv   = (const float*)d_in[11];
    float* out = (float*)d_out;

    cudaFuncSetAttribute(gemm_kernel,
                         cudaFuncAttributeMaxDynamicSharedMemorySize, SMEM_DYN);

    split_text_kernel<<<(M_TOT * DM) / 8 / 256, 256>>>(text);
    wsplit_kernel<<<dim3(DM / 32, DM / 32), dim3(32, 8)>>>(Wt);
    va_kernel<<<BATCH, DM>>>(ac, Wa, ba, Wv, bv);

    gemm_kernel<<<dim3(DM / BN, M_TOT / BM), 512, SMEM_DYN>>>(bt, out);
}

// round 17
// speedup vs baseline: 2.0304x; 1.0509x over previous
#include <cuda_runtime.h>
#include <cuda_fp16.h>
#include <cstdint>

// ===========================================================================
// CrossModalAttention collapses analytically:
//   fa[b,s,:] constant over s => K_a, V_a constant over t
//   => softmax uniform => attn_out[b,s,:] == va[b,:]
//   => out = text @ Wt + bt + va[b]      (one real GEMM)
// Round 17: pure fp16 single-product GEMM (round-16 WIN) at 2 CTAs/SM.
// Clean experiment vs round 5's confounded 2-CTA attempt: ONLY the CTA
// shape changes (BM 256->128, 256 thr, 8 warps 2x4, stage 32KB x2 = 64KB
// -> 2 co-resident CTAs overlap barrier drains). KT=64, SW128, 64x32 warp
// tiles, epilogue prefetch, .cs stores all unchanged.
// ===========================================================================

#define BATCH 8
#define SEQ   2048
#define DM    768
#define DAUD  16
#define M_TOT (BATCH * SEQ)

__device__ float g_va[BATCH * DM];
__device__ __half g_A[M_TOT * DM];         // text as fp16
__device__ __half g_B[DM * DM];            // Wt transposed [N,K], fp16

// ------------------------------ helpers ------------------------------------
__device__ __forceinline__ uint32_t smem_u32(const void* p) {
    uint32_t r;
    asm("{ .reg .u64 t; cvta.to.shared.u64 t, %1; cvt.u32.u64 %0, t; }"
        : "=r"(r) : "l"(p));
    return r;
}

#define SWZ(o) ((o) ^ (((o) >> 3) & 0x70))

__device__ __forceinline__ void cpasync16(uint32_t dst, const void* src) {
    asm volatile("cp.async.cg.shared.global [%0], [%1], 16;"
                 :: "r"(dst), "l"(src));
}

__device__ __forceinline__ void ldsm4(uint32_t* r, uint32_t addr) {
    asm volatile("ldmatrix.sync.aligned.m8n8.x4.shared.b16 {%0,%1,%2,%3}, [%4];"
                 : "=r"(r[0]), "=r"(r[1]), "=r"(r[2]), "=r"(r[3])
                 : "r"(addr));
}

__device__ __forceinline__ void mma16816(float* d,
                                         const uint32_t* a,
                                         uint32_t b0, uint32_t b1) {
    asm volatile(
        "mma.sync.aligned.m16n8k16.row.col.f32.f16.f16.f32 "
        "{%0,%1,%2,%3}, {%4,%5,%6,%7}, {%8,%9}, {%0,%1,%2,%3};"
        : "+f"(d[0]), "+f"(d[1]), "+f"(d[2]), "+f"(d[3])
        : "r"(a[0]), "r"(a[1]), "r"(a[2]), "r"(a[3]), "r"(b0), "r"(b1));
}

__device__ __forceinline__ void stg_cs_v2(float* p, float x, float y) {
    asm volatile("st.global.cs.v2.f32 [%0], {%1, %2};"
                 :: "l"(p), "f"(x), "f"(y) : "memory");
}

// ---------------------------------------------------------------------------
// Prep A: fp32 text -> fp16, 8 elems/thread, one 16B store.
// ---------------------------------------------------------------------------
__global__ void split_text_kernel(const float* __restrict__ x) {
    size_t i = ((size_t)blockIdx.x * blockDim.x + threadIdx.x) * 8;
    float4 v0 = *(const float4*)(x + i);
    float4 v1 = *(const float4*)(x + i + 4);
    __half2 h[4];
    h[0] = __float22half2_rn(make_float2(v0.x, v0.y));
    h[1] = __float22half2_rn(make_float2(v0.z, v0.w));
    h[2] = __float22half2_rn(make_float2(v1.x, v1.y));
    h[3] = __float22half2_rn(make_float2(v1.z, v1.w));
    *(uint4*)(g_A + i) = *(const uint4*)h;
}

// ---------------------------------------------------------------------------
// Prep B: transpose + fp16 convert Wt[K,N] -> g_B [N,K]
// ---------------------------------------------------------------------------
__global__ void wsplit_kernel(const float* __restrict__ W) {
    __shared__ float tile[32][33];
    int n0 = blockIdx.x * 32, k0 = blockIdx.y * 32;
    int tx = threadIdx.x, ty = threadIdx.y;
    for (int r = ty; r < 32; r += 8)
        tile[r][tx] = W[(size_t)(k0 + r) * DM + n0 + tx];
    __syncthreads();
    for (int r = ty; r < 32; r += 8)
        g_B[(size_t)(n0 + r) * DM + k0 + tx] = __float2half_rn(tile[tx][r]);
}

// ---------------------------------------------------------------------------
// Prep C: va[b,:] = (acoustic[b,:] @ Wa + ba) @ Wv + bv
// ---------------------------------------------------------------------------
__global__ void va_kernel(const float* __restrict__ ac,
                          const float* __restrict__ Wa,
                          const float* __restrict__ ba,
                          const float* __restrict__ Wv,
                          const float* __restrict__ bv) {
    __shared__ float fa[DM];
    __shared__ float acs[DAUD];
    const int b = blockIdx.x;
    const int t = threadIdx.x;
    if (t < DAUD) acs[t] = ac[b * DAUD + t];
    __syncthreads();
    float v = ba[t];
#pragma unroll
    for (int k = 0; k < DAUD; k++) v += acs[k] * Wa[k * DM + t];
    fa[t] = v;
    __syncthreads();
    float o = bv[t];
    for (int e = 0; e < DM; e++) o += fa[e] * Wv[e * DM + t];
    g_va[b * DM + t] = o;
}

// ---------------------------------------------------------------------------
// GEMM: CTA tile 128x128, 256 threads (8 warps, 2x4), warp tile 64x32.
// KT=64 chunks, 2-stage cp.async ring, SW128 smem, 2 CTAs/SM.
// Stage (32 KB): A fp16 [128x64] 16 KB, B fp16 [128x64] 16 KB.
// ---------------------------------------------------------------------------
#define BM      128
#define BN      128
#define KT      64
#define KSTEPS  4
#define NCHUNK  (DM / KT)                 // 12
#define TILE_A  (BM * 128)                // 16 KB (128 rows x 128B)
#define TILE_B  (BN * 128)                // 16 KB
#define STAGEB  (TILE_A + TILE_B)         // 32 KB
#define SMEM_DYN (2 * STAGEB)             // 64 KB

__device__ __forceinline__ void load_chunk(uint32_t stg,
                                           const __half* __restrict__ gA,
                                           const __half* __restrict__ gB,
                                           int k0, int tid) {
    // A: 1024 x 16B lines (16 KB)
#pragma unroll
    for (int j = 0; j < 4; j++) {
        const int q = tid + j * 256;              // 0..1023
        const int row = q >> 3, cc = q & 7;
        cpasync16(stg + SWZ(row * 128 + cc * 16),
                  gA + (size_t)row * DM + k0 + cc * 8);
    }
    // B: 1024 lines (16 KB)
#pragma unroll
    for (int j = 0; j < 4; j++) {
        const int q = tid + j * 256;              // 0..1023
        const int row = q >> 3, cc = q & 7;
        cpasync16(stg + TILE_A + SWZ(row * 128 + cc * 16),
                  gB + (size_t)row * DM + k0 + cc * 8);
    }
    asm volatile("cp.async.commit_group;");
}

__global__ __launch_bounds__(256, 2)
void gemm_kernel(const float* __restrict__ bias, float* __restrict__ out) {
    extern __shared__ char dynsmem[];
    const uint32_t base = smem_u32(dynsmem);

    const int tid = threadIdx.x;
    const int wid = tid >> 5, lane = tid & 31;
    const int wm = wid >> 2, wn = wid & 3;   // 2x4 warp grid, 64x32 tiles
    const int bn = blockIdx.x, bm = blockIdx.y;

    const __half* gA = g_A + (size_t)bm * BM * DM;
    const __half* gB = g_B + (size_t)bn * BN * DM;

    float acc[4][4][4] = {};

    load_chunk(base + 0 * STAGEB, gA, gB, 0 * KT, tid);
    load_chunk(base + 1 * STAGEB, gA, gB, 1 * KT, tid);

    // Prefetch epilogue addends while the pipeline fills.
    const int bidx = bm >> 4;                // (bm*128)/2048
    float addv[4][2];
#pragma unroll
    for (int nt = 0; nt < 4; nt++) {
        const int col = bn * BN + wn * 32 + nt * 8 + (lane & 3) * 2;
        addv[nt][0] = bias[col]     + g_va[bidx * DM + col];
        addv[nt][1] = bias[col + 1] + g_va[bidx * DM + col + 1];
    }

    for (int c = 0; c < NCHUNK; ++c) {
        asm volatile("cp.async.wait_group 1;");
        __syncthreads();

        const uint32_t stg = base + (c & 1) * STAGEB;
        const uint32_t As = stg;
        const uint32_t Bs = stg + TILE_A;

#pragma unroll
        for (int ks = 0; ks < KSTEPS; ks++) {
            uint32_t ah[4][4];
            const int akb = ks * 32 + (lane >> 4) * 16;
#pragma unroll
            for (int mt = 0; mt < 4; mt++) {
                const int row = wm * 64 + mt * 16 + (lane & 15);
                ldsm4(ah[mt], As + SWZ(row * 128 + akb));
            }
            const int brow_base = wn * 32 + (lane & 7) + ((lane >> 4) << 3);
            const int bkb = ks * 32 + ((lane >> 3) & 1) * 16;
#pragma unroll
            for (int p = 0; p < 2; p++) {
                uint32_t bh[4];
                ldsm4(bh, Bs + SWZ((brow_base + p * 16) * 128 + bkb));
#pragma unroll
                for (int mt = 0; mt < 4; mt++) {
                    mma16816(acc[mt][2 * p],     ah[mt], bh[0], bh[1]);
                    mma16816(acc[mt][2 * p + 1], ah[mt], bh[2], bh[3]);
                }
            }
        }
        __syncthreads();
        if (c + 2 < NCHUNK)
            load_chunk(stg, gA, gB, (c + 2) * KT, tid);
        else
            asm volatile("cp.async.commit_group;");   // keep group count in step
    }

    // Epilogue: out = acc + (bias + va), streaming stores.
#pragma unroll
    for (int mt = 0; mt < 4; mt++) {
        const int r0 = bm * BM + wm * 64 + mt * 16 + (lane >> 2);
#pragma unroll
        for (int nt = 0; nt < 4; nt++) {
            const int col = bn * BN + wn * 32 + nt * 8 + (lane & 3) * 2;
            stg_cs_v2(out + (size_t)r0 * DM + col,
                      acc[mt][nt][0] + addv[nt][0],
                      acc[mt][nt][1] + addv[nt][1]);
            stg_cs_v2(out + (size_t)(r0 + 8) * DM + col,
                      acc[mt][nt][2] + addv[nt][0],
                      acc[mt][nt][3] + addv[nt][1]);
        }
    }
}

// ---------------------------------------------------------------------------
// Launch. Input order: text, acoustic, Wt, bt, Wa, ba, Wq,bq, Wk,bk, Wv,bv
// ---------------------------------------------------------------------------
extern "C" void kernel_launch(void* const* d_in, const int* in_sizes, int n_in,
                              void* d_out, int out_size) {
    const float* text = (const float*)d_in[0];
    const float* ac   = (const float*)d_in[1];
    const float* Wt   = (const float*)d_in[2];
    const float* bt   = (const float*)d_in[3];
    const float* Wa   = (const float*)d_in[4];
    const float* ba   = (const float*)d_in[5];
    const float* Wv   = (const float*)d_in[10];
    const float* bv   = (const float*)d_in[11];
    float* out = (float*)d_out;

    cudaFuncSetAttribute(gemm_kernel,
                         cudaFuncAttributeMaxDynamicSharedMemorySize, SMEM_DYN);

    split_text_kernel<<<(M_TOT * DM) / 8 / 256, 256>>>(text);
    wsplit_kernel<<<dim3(DM / 32, DM / 32), dim3(32, 8)>>>(Wt);
    va_kernel<<<BATCH, DM>>>(ac, Wa, ba, Wv, bv);

    gemm_kernel<<<dim3(DM / BN, M_TOT / BM), 256, SMEM_DYN>>>(bt, out);
}